// round 12
// baseline (speedup 1.0000x reference)
#include <cuda_runtime.h>
#include <math.h>
#include <stdint.h>

#define BATCH   1024
#define SDIM    2048
#define N_ITER  16
#define KCHUNK  16
#define NCHUNK  (SDIM / KCHUNK)    // 128
#define NTTILES (SDIM / 8)         // 256

// ---------------- static device scratch ----------------
__device__ __align__(256) float g_yth[BATCH * SDIM];
__device__ __align__(256) float g_ydl[BATCH * SDIM];
__device__ __align__(256) float g_xth[BATCH * SDIM];
__device__ __align__(256) float g_xdl[BATCH * SDIM];
__device__ __align__(256) float g_u  [BATCH * SDIM];
__device__ __align__(256) float g_WT [SDIM * SDIM];
__device__ __align__(256) float g_MA [SDIM * SDIM];
__device__ __align__(256) float g_MB [SDIM * SDIM];
__device__ __align__(256) uint4 g_FW [NTTILES * NCHUNK * 32];   // W  B-frags
__device__ __align__(256) uint4 g_FWT[NTTILES * NCHUNK * 32];   // WT B-frags
__device__ __align__(256) uint4 g_FMA[NTTILES * NCHUNK * 32];   // eigen intermediate frags
__device__ __align__(256) uint4 g_FMB[NTTILES * NCHUNK * 32];
__device__ __align__(256) float g_vec [SDIM];
__device__ __align__(256) float g_wvec[SDIM];
__device__ float g_scal[4];   // [0] = 1/L, [1] = thresh

// SMEM: A stage s at s*4096 (hi +0, lo +2048); B stage s at 8192 + s*8192
#define B_BASE     8192
#define SMEM_TOTAL 24576   // 24 KB -> 3 CTAs/SM

static __device__ __forceinline__ uint32_t smem_u32(const void* p) {
    uint32_t a;
    asm("{ .reg .u64 t; cvta.to.shared.u64 t, %1; cvt.u32.u64 %0, t; }" : "=r"(a) : "l"(p));
    return a;
}
static __device__ __forceinline__ uint32_t lds32(uint32_t a) {
    uint32_t v; asm volatile("ld.shared.b32 %0, [%1];" : "=r"(v) : "r"(a)); return v;
}
static __device__ __forceinline__ void lds128(uint4& r, uint32_t a) {
    asm volatile("ld.shared.v4.b32 {%0,%1,%2,%3}, [%4];"
                 : "=r"(r.x), "=r"(r.y), "=r"(r.z), "=r"(r.w) : "r"(a));
}
static __device__ __forceinline__ void sts64(uint32_t a, uint32_t v0, uint32_t v1) {
    asm volatile("st.shared.v2.b32 [%0], {%1,%2};" :: "r"(a), "r"(v0), "r"(v1));
}
static __device__ __forceinline__ void cpasync16(uint32_t smem, const void* g) {
    asm volatile("cp.async.cg.shared.global [%0], [%1], 16;" :: "r"(smem), "l"(g));
}
static __device__ __forceinline__ void cpasync_commit() {
    asm volatile("cp.async.commit_group;" ::: "memory");
}
static __device__ __forceinline__ void cpasync_wait0() {
    asm volatile("cp.async.wait_group 0;" ::: "memory");
}
static __device__ __forceinline__ void mma16816(float* d, const uint32_t* a,
                                                uint32_t b0, uint32_t b1) {
    asm volatile(
        "mma.sync.aligned.m16n8k16.row.col.f32.bf16.bf16.f32 "
        "{%0,%1,%2,%3}, {%4,%5,%6,%7}, {%8,%9}, {%0,%1,%2,%3};"
        : "+f"(d[0]), "+f"(d[1]), "+f"(d[2]), "+f"(d[3])
        : "r"(a[0]), "r"(a[1]), "r"(a[2]), "r"(a[3]), "r"(b0), "r"(b1));
}

// split float4 -> 2 packed bf16x2 hi (truncated) + 2 lo (rounded residual)
static __device__ __forceinline__ void split4(float4 v, uint32_t& h0, uint32_t& h1,
                                              uint32_t& l0, uint32_t& l1) {
    uint32_t u0 = __float_as_uint(v.x), u1 = __float_as_uint(v.y);
    uint32_t u2 = __float_as_uint(v.z), u3 = __float_as_uint(v.w);
    h0 = __byte_perm(u0, u1, 0x7632);
    h1 = __byte_perm(u2, u3, 0x7632);
    float a0 = v.x - __uint_as_float(u0 & 0xFFFF0000u);
    float a1 = v.y - __uint_as_float(u1 & 0xFFFF0000u);
    float a2 = v.z - __uint_as_float(u2 & 0xFFFF0000u);
    float a3 = v.w - __uint_as_float(u3 & 0xFFFF0000u);
    asm("cvt.rn.bf16x2.f32 %0, %1, %2;" : "=r"(l0) : "f"(a1), "f"(a0));
    asm("cvt.rn.bf16x2.f32 %0, %1, %2;" : "=r"(l1) : "f"(a3), "f"(a2));
}

// pack pair (x -> low half, y -> high half)
static __device__ __forceinline__ void pack2(float x, float y, uint32_t& h, uint32_t& l) {
    uint32_t ux = __float_as_uint(x), uy = __float_as_uint(y);
    h = __byte_perm(ux, uy, 0x7632);
    float r0 = x - __uint_as_float(ux & 0xFFFF0000u);
    float r1 = y - __uint_as_float(uy & 0xFFFF0000u);
    asm("cvt.rn.bf16x2.f32 %0, %1, %2;" : "=r"(l) : "f"(r1), "f"(r0));
}

static __device__ __forceinline__ float softthr(float v, float th) {
    float a = fabsf(v) - th;
    return a > 0.0f ? copysignf(a, v) : 0.0f;
}

// ---------------------------------------------------------------------------
// Unified GEMM: C[m,n] = sum_k A[m,k]*B[n,k], K=2048. CTA tile 64(M)x128(N),
// 4 warps (2x2), warp tile 32x64. A: fp32 via smem (split in-kernel);
// B: pre-split frag array staged gmem->smem via cp.async, LDS.128 to regs.
// SYM=1 (EPI 0): triangular macro grid + mirror; C = acc*scale.
// EPI 1: GEMM1 epilogue: res in regs -> u, delta soft-threshold update (+out)
// EPI 2: GEMM2 epilogue: theta soft-threshold update (+out)
// ---------------------------------------------------------------------------
template<int EPI, int SYM>
__global__ void __launch_bounds__(128, 3)
gemm_bf(const float* __restrict__ A, const uint4* __restrict__ FB,
        float* __restrict__ C, float scale,
        const float* __restrict__ src, const float* __restrict__ Yg,
        float* __restrict__ xth, float* __restrict__ yth,
        float* __restrict__ xdl, float* __restrict__ ydl,
        float* __restrict__ outp, float mom)
{
    extern __shared__ char smem[];
    const uint32_t sb = smem_u32(smem);
    const int tid = threadIdx.x;
    const int wid = tid >> 5, lid = tid & 31;
    const int wm = wid & 1, wn = wid >> 1;

    int row0, col0;
    bool mirror = false;
    if (SYM) {
        int bid = blockIdx.x;
        int mac = bid >> 1, half0 = bid & 1;
        int by = (int)((sqrtf(8.0f * mac + 1.0f) - 1.0f) * 0.5f);
        while ((by + 1) * (by + 2) / 2 <= mac) by++;
        while (by * (by + 1) / 2 > mac) by--;
        int bx = mac - by * (by + 1) / 2;
        row0 = by * 128 + half0 * 64;
        col0 = bx * 128;
        mirror = (bx != by);
    } else {
        row0 = blockIdx.y * 64;
        col0 = blockIdx.x * 128;
    }

    // A producer mapping (coalesced LDG, conflict-free STS.64)
    const int qa = tid & 3;
    const int rbase = tid >> 2;
    const int hp = qa >> 1, q1 = qa & 1;
    uint32_t aOff[2];
#pragma unroll
    for (int p = 0; p < 2; p++) {
        int r = rbase + 32 * p;
        int mt = r >> 4, rr = r & 15, rrq = rr & 7, r8 = rr >> 3;
        aOff[p] = (uint32_t)(((mt * 4 + hp * 2 + r8) * 32 + rrq * 4 + 2 * q1) * 4);
    }
    const float* Abase = A + (size_t)(row0 + rbase) * SDIM + qa * 4;

    // B producer mapping: 16 nt-tiles x 32 lanes = 512 uint4 per chunk;
    // each thread cp.asyncs 4 (elements tid + p*128)
    const int nt0 = col0 >> 3;
    const uint4* Bg[4];
    uint32_t bDst[4];
#pragma unroll
    for (int p = 0; p < 4; p++) {
        int e = tid + p * 128;
        Bg[p]   = FB + ((size_t)(nt0 + (e >> 5)) * NCHUNK) * 32 + (e & 31);
        bDst[p] = sb + B_BASE + (uint32_t)(e * 16);
    }

    float acc[2][8][4];
#pragma unroll
    for (int i = 0; i < 2; i++)
#pragma unroll
        for (int j = 0; j < 8; j++)
#pragma unroll
            for (int q = 0; q < 4; q++) acc[i][j][q] = 0.0f;

    float4 pA[2];

#define F_LDGA(kt)                                                                 \
    do {                                                                           \
        _Pragma("unroll")                                                          \
        for (int p = 0; p < 2; p++)                                                \
            pA[p] = *reinterpret_cast<const float4*>(Abase + (size_t)(32 * p) * SDIM + (kt)); \
    } while (0)

#define F_STSA(stoff)                                                              \
    do {                                                                           \
        _Pragma("unroll")                                                          \
        for (int p = 0; p < 2; p++) {                                              \
            uint32_t h0, h1, l0, l1;                                               \
            split4(pA[p], h0, h1, l0, l1);                                         \
            sts64(sb + (stoff) + aOff[p], h0, h1);                                 \
            sts64(sb + (stoff) + 2048u + aOff[p], l0, l1);                         \
        }                                                                          \
    } while (0)

#define F_CPAB(stage, cc)                                                          \
    do {                                                                           \
        _Pragma("unroll")                                                          \
        for (int p = 0; p < 4; p++)                                                \
            cpasync16(bDst[p] + (uint32_t)((stage) * 8192), Bg[p] + (size_t)(cc) * 32); \
        cpasync_commit();                                                          \
    } while (0)

#define F_CONSUME(aoff, boff)                                                      \
    do {                                                                           \
        uint32_t ah[2][4], al[2][4];                                               \
        _Pragma("unroll")                                                          \
        for (int bm = 0; bm < 2; bm++) {                                           \
            int mt = wm * 2 + bm;                                                  \
            uint32_t ab = sb + (aoff) + (uint32_t)((mt * 4) * 128) + l4;           \
            _Pragma("unroll")                                                      \
            for (int wi = 0; wi < 4; wi++) {                                       \
                ah[bm][wi] = lds32(ab + wi * 128);                                 \
                al[bm][wi] = lds32(ab + 2048u + wi * 128);                         \
            }                                                                      \
        }                                                                          \
        uint4 bf[8];                                                               \
        _Pragma("unroll")                                                          \
        for (int t = 0; t < 8; t++)                                                \
            lds128(bf[t], sb + B_BASE + (boff) +                                   \
                   (uint32_t)((((wn * 8 + t) * 32 + lid)) * 16));                  \
        _Pragma("unroll")                                                          \
        for (int bm = 0; bm < 2; bm++)                                             \
            _Pragma("unroll")                                                      \
            for (int t = 0; t < 8; t++)                                            \
                mma16816(acc[bm][t], ah[bm], bf[t].x, bf[t].y);                    \
        _Pragma("unroll")                                                          \
        for (int bm = 0; bm < 2; bm++)                                             \
            _Pragma("unroll")                                                      \
            for (int t = 0; t < 8; t++)                                            \
                mma16816(acc[bm][t], ah[bm], bf[t].z, bf[t].w);                    \
        _Pragma("unroll")                                                          \
        for (int bm = 0; bm < 2; bm++)                                             \
            _Pragma("unroll")                                                      \
            for (int t = 0; t < 8; t++)                                            \
                mma16816(acc[bm][t], al[bm], bf[t].x, bf[t].y);                    \
    } while (0)

    const uint32_t l4 = (uint32_t)(lid * 4);

    // prologue: chunk 0 into stage 0
    F_LDGA(0);
    F_CPAB(0, 0);
    F_STSA(0u);
    cpasync_wait0();
    __syncthreads();

#pragma unroll 1
    for (int c = 0; c < NCHUNK; c++) {
        const int cur = c & 1, nxt = cur ^ 1;
        if (c + 1 < NCHUNK) {
            F_LDGA((c + 1) * KCHUNK);
            F_CPAB(nxt, c + 1);
        }
        F_CONSUME((uint32_t)(cur * 4096), (uint32_t)(cur * 8192));
        if (c + 1 < NCHUNK) F_STSA((uint32_t)(nxt * 4096));
        cpasync_wait0();
        __syncthreads();
    }

    // ---- epilogue ----
    const float invL = (EPI != 0) ? g_scal[0] : 0.0f;
    const float th   = (EPI != 0) ? g_scal[1] : 0.0f;
    const int gid = lid >> 2, tig = lid & 3;
#pragma unroll
    for (int bm = 0; bm < 2; bm++) {
#pragma unroll
        for (int bn = 0; bn < 8; bn++) {
            const int n = col0 + wn * 64 + bn * 8 + tig * 2;
#pragma unroll
            for (int hr = 0; hr < 2; hr++) {
                const int m = row0 + wm * 32 + bm * 16 + gid + hr * 8;
                float ax = acc[bm][bn][hr * 2 + 0];
                float ay = acc[bm][bn][hr * 2 + 1];
                const size_t idx = (size_t)m * SDIM + n;
                if (EPI == 0) {
                    ax *= scale; ay *= scale;
                    float2 o; o.x = ax; o.y = ay;
                    *reinterpret_cast<float2*>(C + idx) = o;
                    if (SYM && mirror) {
                        C[(size_t)n * SDIM + m]       = ax;
                        C[(size_t)(n + 1) * SDIM + m] = ay;
                    }
                } else if (EPI == 1) {
                    // res in regs -> u store + delta FISTA update
                    float2 s  = *reinterpret_cast<const float2*>(src + idx);
                    float2 yv = *reinterpret_cast<const float2*>(Yg + idx);
                    float2 yd = *reinterpret_cast<const float2*>(ydl + idx);
                    float2 xd = *reinterpret_cast<const float2*>(xdl + idx);
                    float rx = yv.x - s.x * ax - yd.x;
                    float ry = yv.y - s.y * ay - yd.y;
                    float2 uu; uu.x = s.x * rx; uu.y = s.y * ry;
                    *reinterpret_cast<float2*>(C + idx) = uu;   // C = u buffer
                    float2 xnd, ynd;
                    xnd.x = softthr(yd.x + rx * invL, th);  ynd.x = xnd.x + mom * (xnd.x - xd.x);
                    xnd.y = softthr(yd.y + ry * invL, th);  ynd.y = xnd.y + mom * (xnd.y - xd.y);
                    *reinterpret_cast<float2*>(xdl + idx) = xnd;
                    *reinterpret_cast<float2*>(ydl + idx) = ynd;
                    if (outp) {
                        const size_t ob = (size_t)m * (2 * SDIM) + SDIM + n;
                        *reinterpret_cast<float2*>(outp + ob) = xnd;
                    }
                } else {
                    // theta FISTA update
                    float2 yt = *reinterpret_cast<const float2*>(yth + idx);
                    float2 xt = *reinterpret_cast<const float2*>(xth + idx);
                    float2 xn, yn;
                    xn.x = softthr(yt.x + ax * invL, th);  yn.x = xn.x + mom * (xn.x - xt.x);
                    xn.y = softthr(yt.y + ay * invL, th);  yn.y = xn.y + mom * (xn.y - xt.y);
                    *reinterpret_cast<float2*>(xth + idx) = xn;
                    *reinterpret_cast<float2*>(yth + idx) = yn;
                    if (outp) {
                        const size_t ob = (size_t)m * (2 * SDIM) + n;
                        *reinterpret_cast<float2*>(outp + ob) = xn;
                    }
                }
            }
        }
    }
}

// ---------------------------------------------------------------------------
// B-frag builder: F[(nt*NCHUNK + c)*32 + lane] = {hi_k0, hi_k8, lo_k0, lo_k8}
// 256 threads: 8 n-tiles per block.
// ---------------------------------------------------------------------------
__global__ void build_bfrag(const float* __restrict__ B, uint4* __restrict__ F) {
    int l  = threadIdx.x & 31;
    int nt = blockIdx.x * 8 + (threadIdx.x >> 5);
    int c  = blockIdx.y;
    int n  = nt * 8 + (l >> 2);
    int k0 = c * KCHUNK + (l & 3) * 2;
    const float* row = B + (size_t)n * SDIM;
    uint4 w;
    uint32_t lz, lw;
    pack2(row[k0],     row[k0 + 1], w.x, lz);
    pack2(row[k0 + 8], row[k0 + 9], w.y, lw);
    w.z = lz; w.w = lw;
    F[((size_t)nt * NCHUNK + c) * 32 + l] = w;
}

// ---------------- helper kernels ----------------
__global__ void transpose_kernel(const float* __restrict__ in, float* __restrict__ out) {
    __shared__ float t[32][33];
    int bx = blockIdx.x * 32, by = blockIdx.y * 32;
    int x = bx + threadIdx.x;
#pragma unroll
    for (int i = threadIdx.y; i < 32; i += 8)
        t[i][threadIdx.x] = in[(size_t)(by + i) * SDIM + x];
    __syncthreads();
    int x2 = by + threadIdx.x;
#pragma unroll
    for (int i = threadIdx.y; i < 32; i += 8)
        out[(size_t)(bx + i) * SDIM + x2] = t[threadIdx.x][i];
}

// iter0: y=0 -> r=Y ; u=src*Y ; delta step0 (mom=0): xdl=ydl=soft(Y*invL, th)
__global__ void init_iter0_kernel(const float* __restrict__ src, const float* __restrict__ Yg,
                                  float* __restrict__ uv,
                                  float* __restrict__ xdl, float* __restrict__ ydl) {
    int i = blockIdx.x * blockDim.x + threadIdx.x;
    const float invL = g_scal[0], th = g_scal[1];
    float4 y = reinterpret_cast<const float4*>(Yg)[i];
    float4 s = reinterpret_cast<const float4*>(src)[i];
    float4 u; u.x = s.x * y.x; u.y = s.y * y.y; u.z = s.z * y.z; u.w = s.w * y.w;
    reinterpret_cast<float4*>(uv)[i] = u;
    float4 x;
    x.x = softthr(y.x * invL, th);
    x.y = softthr(y.y * invL, th);
    x.z = softthr(y.z * invL, th);
    x.w = softthr(y.w * invL, th);
    reinterpret_cast<float4*>(xdl)[i] = x;
    reinterpret_cast<float4*>(ydl)[i] = x;
}

__global__ void fill_kernel() {
    int i = blockIdx.x * blockDim.x + threadIdx.x;
    if (i < SDIM) {
        unsigned h = (unsigned)i * 2654435761u;
        h ^= h >> 13; h *= 2246822519u; h ^= h >> 16;
        g_vec[i] = (float)(h & 0xFFFF) / 65536.0f - 0.5f;
    }
}

__global__ void matvec_kernel(const float* __restrict__ H,
                              const float* __restrict__ x,
                              float* __restrict__ y) {
    int row = blockIdx.x;
    const float* hr = H + (size_t)row * SDIM;
    float s = 0.0f;
    for (int j = threadIdx.x; j < SDIM; j += 256) s += hr[j] * x[j];
#pragma unroll
    for (int o = 16; o > 0; o >>= 1) s += __shfl_xor_sync(0xffffffffu, s, o);
    __shared__ float part[8];
    int w = threadIdx.x >> 5;
    if ((threadIdx.x & 31) == 0) part[w] = s;
    __syncthreads();
    if (threadIdx.x == 0) {
        float t = 0.0f;
#pragma unroll
        for (int k = 0; k < 8; k++) t += part[k];
        y[row] = t;
    }
}

__global__ void normalize_kernel(const float* __restrict__ w, float* __restrict__ v) {
    float ss = 0.0f;
    for (int i = threadIdx.x; i < SDIM; i += 256) { float t = w[i]; ss += t * t; }
#pragma unroll
    for (int o = 16; o > 0; o >>= 1) ss += __shfl_xor_sync(0xffffffffu, ss, o);
    __shared__ float part[8];
    __shared__ float s_inv;
    int wd = threadIdx.x >> 5;
    if ((threadIdx.x & 31) == 0) part[wd] = ss;
    __syncthreads();
    if (threadIdx.x == 0) {
        float t = 0.0f;
        for (int i = 0; i < 8; i++) t += part[i];
        s_inv = rsqrtf(t);
    }
    __syncthreads();
    float inv = s_inv;
    for (int i = threadIdx.x; i < SDIM; i += 256) v[i] = w[i] * inv;
}

// Rayleigh on G'^64 (G' = G/4): L = 4 * lam^(1/64); writes 1/L and thresh.
__global__ void finalize_kernel(const float* __restrict__ v,
                                const float* __restrict__ w,
                                const float* __restrict__ alpha) {
    float num = 0.0f, den = 0.0f;
    for (int i = threadIdx.x; i < SDIM; i += 256) { num += v[i] * w[i]; den += v[i] * v[i]; }
#pragma unroll
    for (int o = 16; o > 0; o >>= 1) {
        num += __shfl_xor_sync(0xffffffffu, num, o);
        den += __shfl_xor_sync(0xffffffffu, den, o);
    }
    __shared__ float pn[8], pd[8];
    int wd = threadIdx.x >> 5;
    if ((threadIdx.x & 31) == 0) { pn[wd] = num; pd[wd] = den; }
    __syncthreads();
    if (threadIdx.x == 0) {
        double n = 0.0, d = 0.0;
        for (int i = 0; i < 8; i++) { n += pn[i]; d += pd[i]; }
        double lam = n / d;
        double L = 4.0 * pow(lam, 1.0 / 64.0);
        g_scal[0] = (float)(1.0 / L);
        g_scal[1] = (float)((double)alpha[0] * 0.5 / L);
    }
}

#define NSYMT (136 * 2)
#define FNULL nullptr, nullptr, nullptr, nullptr, nullptr, nullptr, nullptr, 0.0f

extern "C" void kernel_launch(void* const* d_in, const int* in_sizes, int n_in,
                              void* d_out, int out_size) {
    (void)in_sizes; (void)n_in; (void)out_size;
    const float* src   = (const float*)d_in[0];
    const float* Y     = (const float*)d_in[1];
    const float* W     = (const float*)d_in[2];
    const float* alpha = (const float*)d_in[3];
    float* out = (float*)d_out;

    float *yth, *ydl, *xth, *xdl, *u, *WT, *MA, *MB, *vec, *wvec;
    uint4 *FW, *FWT, *FMA, *FMB;
    cudaGetSymbolAddress((void**)&yth,  g_yth);
    cudaGetSymbolAddress((void**)&ydl,  g_ydl);
    cudaGetSymbolAddress((void**)&xth,  g_xth);
    cudaGetSymbolAddress((void**)&xdl,  g_xdl);
    cudaGetSymbolAddress((void**)&u,    g_u);
    cudaGetSymbolAddress((void**)&WT,   g_WT);
    cudaGetSymbolAddress((void**)&MA,   g_MA);
    cudaGetSymbolAddress((void**)&MB,   g_MB);
    cudaGetSymbolAddress((void**)&FW,   g_FW);
    cudaGetSymbolAddress((void**)&FWT,  g_FWT);
    cudaGetSymbolAddress((void**)&FMA,  g_FMA);
    cudaGetSymbolAddress((void**)&FMB,  g_FMB);
    cudaGetSymbolAddress((void**)&vec,  g_vec);
    cudaGetSymbolAddress((void**)&wvec, g_wvec);

    // WT = W^T, then B-frag splits of W and WT
    transpose_kernel<<<dim3(64, 64), dim3(32, 8)>>>(W, WT);
    build_bfrag<<<dim3(NTTILES / 8, NCHUNK), 256>>>(W, FW);
    build_bfrag<<<dim3(NTTILES / 8, NCHUNK), 256>>>(WT, FWT);

    // eigen chain: G' = (W^T W)/4, then 6 squarings -> G'^64 in MA.
    gemm_bf<0, 1><<<NSYMT, 128, SMEM_TOTAL>>>(WT, FWT, MA, 0.25f, FNULL);
    build_bfrag<<<dim3(NTTILES / 8, NCHUNK), 256>>>(MA, FMA);
    gemm_bf<0, 1><<<NSYMT, 128, SMEM_TOTAL>>>(MA, FMA, MB, 1.0f, FNULL);
    build_bfrag<<<dim3(NTTILES / 8, NCHUNK), 256>>>(MB, FMB);
    gemm_bf<0, 1><<<NSYMT, 128, SMEM_TOTAL>>>(MB, FMB, MA, 1.0f, FNULL);
    build_bfrag<<<dim3(NTTILES / 8, NCHUNK), 256>>>(MA, FMA);
    gemm_bf<0, 1><<<NSYMT, 128, SMEM_TOTAL>>>(MA, FMA, MB, 1.0f, FNULL);
    build_bfrag<<<dim3(NTTILES / 8, NCHUNK), 256>>>(MB, FMB);
    gemm_bf<0, 1><<<NSYMT, 128, SMEM_TOTAL>>>(MB, FMB, MA, 1.0f, FNULL);
    build_bfrag<<<dim3(NTTILES / 8, NCHUNK), 256>>>(MA, FMA);
    gemm_bf<0, 1><<<NSYMT, 128, SMEM_TOTAL>>>(MA, FMA, MB, 1.0f, FNULL);
    build_bfrag<<<dim3(NTTILES / 8, NCHUNK), 256>>>(MB, FMB);
    gemm_bf<0, 1><<<NSYMT, 128, SMEM_TOTAL>>>(MB, FMB, MA, 1.0f, FNULL);

    // power iteration + Rayleigh on G'^64
    fill_kernel<<<(SDIM + 255) / 256, 256>>>();
    for (int i = 0; i < 2; i++) {
        for (int jj = 0; jj < 7; jj++) {
            matvec_kernel<<<SDIM, 256>>>(MA, vec, wvec);
            float* tmp = vec; vec = wvec; wvec = tmp;
        }
        matvec_kernel<<<SDIM, 256>>>(MA, vec, wvec);
        normalize_kernel<<<1, 256>>>(wvec, vec);
    }
    matvec_kernel<<<SDIM, 256>>>(MA, vec, wvec);
    finalize_kernel<<<1, 256>>>(vec, wvec, alpha);

    // FISTA state init: theta halves zero; iter0 shortcut for u + delta step
    size_t bytes = (size_t)BATCH * SDIM * sizeof(float);
    cudaMemsetAsync(yth, 0, bytes);
    cudaMemsetAsync(xth, 0, bytes);
    init_iter0_kernel<<<(BATCH * SDIM / 4 + 255) / 256, 256>>>(src, Y, u, xdl, ydl);

    dim3 ga(SDIM / 128, BATCH / 64);   // 16 x 16 = 256 CTAs

    float t = 1.0f;
    for (int it = 0; it < N_ITER; it++) {
        float tn  = (1.0f + sqrtf(1.0f + 4.0f * t * t)) * 0.5f;
        float mom = (t - 1.0f) / tn;
        t = tn;
        float* op = (it == N_ITER - 1) ? out : nullptr;

        if (it > 0) {
            // GEMM1: Z = yth*W^T ; r = Y - src*Z - ydl (regs) ; u = src*r ;
            //        delta soft-threshold + momentum (+out delta half)
            gemm_bf<1, 0><<<ga, 128, SMEM_TOTAL>>>(yth, FW, u, 0.0f,
                src, Y, nullptr, nullptr, xdl, ydl, op, mom);
        }
        // GEMM2: g = W^T u ; theta soft-threshold + momentum (+out theta half)
        gemm_bf<2, 0><<<ga, 128, SMEM_TOTAL>>>(u, FWT, nullptr, 0.0f,
            nullptr, nullptr, xth, yth, nullptr, nullptr, op, mom);
    }
}

// round 13
// speedup vs baseline: 1.0476x; 1.0476x over previous
#include <cuda_runtime.h>
#include <math.h>
#include <stdint.h>

#define BATCH   1024
#define SDIM    2048
#define N_ITER  16
#define KCHUNK  16
#define NCHUNK  (SDIM / KCHUNK)    // 128
#define NTTILES (SDIM / 8)         // 256
#define NTHREADS 256

// ---------------- static device scratch ----------------
__device__ __align__(256) float g_yth[BATCH * SDIM];
__device__ __align__(256) float g_ydl[BATCH * SDIM];
__device__ __align__(256) float g_xth[BATCH * SDIM];
__device__ __align__(256) float g_xdl[BATCH * SDIM];
__device__ __align__(256) float g_u  [BATCH * SDIM];
__device__ __align__(256) float g_WT [SDIM * SDIM];
__device__ __align__(256) float g_MA [SDIM * SDIM];
__device__ __align__(256) float g_MB [SDIM * SDIM];
__device__ __align__(256) uint4 g_FW [NTTILES * NCHUNK * 32];   // W  B-frags
__device__ __align__(256) uint4 g_FWT[NTTILES * NCHUNK * 32];   // WT B-frags
__device__ __align__(256) uint4 g_FMA[NTTILES * NCHUNK * 32];   // eigen intermediate frags
__device__ __align__(256) uint4 g_FMB[NTTILES * NCHUNK * 32];
__device__ __align__(256) float g_vec [SDIM];
__device__ __align__(256) float g_wvec[SDIM];
__device__ float g_scal[4];   // [0] = 1/L, [1] = thresh

// A-side smem: Ahi[0,2K) Alo[2K,4K), two stages
#define STAGE_BF   4096
#define SMEM_BF    (2 * STAGE_BF)  // 8 KB

static __device__ __forceinline__ uint32_t smem_u32(const void* p) {
    uint32_t a;
    asm("{ .reg .u64 t; cvta.to.shared.u64 t, %1; cvt.u32.u64 %0, t; }" : "=r"(a) : "l"(p));
    return a;
}
static __device__ __forceinline__ uint32_t lds32(uint32_t a) {
    uint32_t v; asm volatile("ld.shared.b32 %0, [%1];" : "=r"(v) : "r"(a)); return v;
}
static __device__ __forceinline__ void sts64(uint32_t a, uint32_t v0, uint32_t v1) {
    asm volatile("st.shared.v2.b32 [%0], {%1,%2};" :: "r"(a), "r"(v0), "r"(v1));
}
static __device__ __forceinline__ void mma16816(float* d, const uint32_t* a,
                                                uint32_t b0, uint32_t b1) {
    asm volatile(
        "mma.sync.aligned.m16n8k16.row.col.f32.bf16.bf16.f32 "
        "{%0,%1,%2,%3}, {%4,%5,%6,%7}, {%8,%9}, {%0,%1,%2,%3};"
        : "+f"(d[0]), "+f"(d[1]), "+f"(d[2]), "+f"(d[3])
        : "r"(a[0]), "r"(a[1]), "r"(a[2]), "r"(a[3]), "r"(b0), "r"(b1));
}

// split float4 -> 2 packed bf16x2 hi (truncated) + 2 lo (rounded residual)
static __device__ __forceinline__ void split4(float4 v, uint32_t& h0, uint32_t& h1,
                                              uint32_t& l0, uint32_t& l1) {
    uint32_t u0 = __float_as_uint(v.x), u1 = __float_as_uint(v.y);
    uint32_t u2 = __float_as_uint(v.z), u3 = __float_as_uint(v.w);
    h0 = __byte_perm(u0, u1, 0x7632);
    h1 = __byte_perm(u2, u3, 0x7632);
    float a0 = v.x - __uint_as_float(u0 & 0xFFFF0000u);
    float a1 = v.y - __uint_as_float(u1 & 0xFFFF0000u);
    float a2 = v.z - __uint_as_float(u2 & 0xFFFF0000u);
    float a3 = v.w - __uint_as_float(u3 & 0xFFFF0000u);
    asm("cvt.rn.bf16x2.f32 %0, %1, %2;" : "=r"(l0) : "f"(a1), "f"(a0));
    asm("cvt.rn.bf16x2.f32 %0, %1, %2;" : "=r"(l1) : "f"(a3), "f"(a2));
}

// pack pair (x -> low half, y -> high half)
static __device__ __forceinline__ void pack2(float x, float y, uint32_t& h, uint32_t& l) {
    uint32_t ux = __float_as_uint(x), uy = __float_as_uint(y);
    h = __byte_perm(ux, uy, 0x7632);
    float r0 = x - __uint_as_float(ux & 0xFFFF0000u);
    float r1 = y - __uint_as_float(uy & 0xFFFF0000u);
    asm("cvt.rn.bf16x2.f32 %0, %1, %2;" : "=r"(l) : "f"(r1), "f"(r0));
}

static __device__ __forceinline__ float softthr(float v, float th) {
    float a = fabsf(v) - th;
    return a > 0.0f ? copysignf(a, v) : 0.0f;
}

// ---------------------------------------------------------------------------
// Unified GEMM: C[m,n] = sum_k A[m,k]*B[n,k], K=2048. CTA tile 64(M)x128(N),
// 8 warps (2x4), warp tile 32x32. A: fp32 via smem (split in-kernel);
// B: pre-split frag array via LDG, register double-buffered.
// SYM=1 (EPI 0): triangular macro grid + mirror; C = acc*scale.
// EPI 1: GEMM1 epilogue: res in regs -> u, delta soft-threshold update (+out)
// EPI 2: GEMM2 epilogue: theta soft-threshold update (+out)
// ---------------------------------------------------------------------------
template<int EPI, int SYM>
__global__ void __launch_bounds__(NTHREADS, 2)
gemm_bf(const float* __restrict__ A, const uint4* __restrict__ FB,
        float* __restrict__ C, float scale,
        const float* __restrict__ src, const float* __restrict__ Yg,
        float* __restrict__ xth, float* __restrict__ yth,
        float* __restrict__ xdl, float* __restrict__ ydl,
        float* __restrict__ outp, float mom)
{
    extern __shared__ char smem[];
    const uint32_t sb = smem_u32(smem);
    const int tid = threadIdx.x;
    const int wid = tid >> 5, lid = tid & 31;
    const int wm = wid & 1, wn = wid >> 1;   // 2 x 4 warps over (M, N)

    int row0, col0;
    bool mirror = false;
    if (SYM) {
        int bid = blockIdx.x;
        int mac = bid >> 1, half0 = bid & 1;
        int by = (int)((sqrtf(8.0f * mac + 1.0f) - 1.0f) * 0.5f);
        while ((by + 1) * (by + 2) / 2 <= mac) by++;
        while (by * (by + 1) / 2 > mac) by--;
        int bx = mac - by * (by + 1) / 2;
        row0 = by * 128 + half0 * 64;
        col0 = bx * 128;
        mirror = (bx != by);
    } else {
        row0 = blockIdx.y * 64;
        col0 = blockIdx.x * 128;
    }

    // A producer mapping: 256 threads, one float4 each (row rbase, cols qa*4..)
    const int qa = tid & 3;
    const int rbase = tid >> 2;              // 0..63
    const int hp = qa >> 1, q1 = qa & 1;
    uint32_t aOff;
    {
        int r = rbase;
        int mt = r >> 4, rr = r & 15, rrq = rr & 7, r8 = rr >> 3;
        aOff = (uint32_t)(((mt * 4 + hp * 2 + r8) * 32 + rrq * 4 + 2 * q1) * 4);
    }
    const float* Abase = A + (size_t)(row0 + rbase) * SDIM + qa * 4;

    // B fragment base for this warp: n-tiles (col0>>3)+wn*4 ..+3
    const uint4* Fbase = FB + ((size_t)((col0 >> 3) + wn * 4) * NCHUNK) * 32 + lid;

    float acc[2][4][4];
#pragma unroll
    for (int i = 0; i < 2; i++)
#pragma unroll
        for (int j = 0; j < 4; j++)
#pragma unroll
            for (int q = 0; q < 4; q++) acc[i][j][q] = 0.0f;

    float4 pA;
    uint4 bE[4], bO[4];

#define F_LDGA(kt)                                                                 \
    do { pA = *reinterpret_cast<const float4*>(Abase + (kt)); } while (0)

#define F_STSA(stoff)                                                              \
    do {                                                                           \
        uint32_t h0, h1, l0, l1;                                                   \
        split4(pA, h0, h1, l0, l1);                                                \
        sts64(sb + (stoff) + aOff, h0, h1);                                        \
        sts64(sb + (stoff) + 2048u + aOff, l0, l1);                                \
    } while (0)

#define F_LDGB(dst, cc)                                                            \
    do {                                                                           \
        _Pragma("unroll")                                                          \
        for (int t = 0; t < 4; t++)                                                \
            dst[t] = Fbase[((size_t)t * NCHUNK + (cc)) * 32];                      \
    } while (0)

#define F_CONSUME(stoff, BFR)                                                      \
    do {                                                                           \
        uint32_t ah[2][4], al[2][4];                                               \
        _Pragma("unroll")                                                          \
        for (int bm = 0; bm < 2; bm++) {                                           \
            int mt = wm * 2 + bm;                                                  \
            uint32_t ab = sb + (stoff) + (uint32_t)((mt * 4) * 128) + l4;          \
            _Pragma("unroll")                                                      \
            for (int wi = 0; wi < 4; wi++) {                                       \
                ah[bm][wi] = lds32(ab + wi * 128);                                 \
                al[bm][wi] = lds32(ab + 2048u + wi * 128);                         \
            }                                                                      \
        }                                                                          \
        _Pragma("unroll")                                                          \
        for (int bm = 0; bm < 2; bm++)                                             \
            _Pragma("unroll")                                                      \
            for (int t = 0; t < 4; t++)                                            \
                mma16816(acc[bm][t], ah[bm], BFR[t].x, BFR[t].y);                  \
        _Pragma("unroll")                                                          \
        for (int bm = 0; bm < 2; bm++)                                             \
            _Pragma("unroll")                                                      \
            for (int t = 0; t < 4; t++)                                            \
                mma16816(acc[bm][t], ah[bm], BFR[t].z, BFR[t].w);                  \
        _Pragma("unroll")                                                          \
        for (int bm = 0; bm < 2; bm++)                                             \
            _Pragma("unroll")                                                      \
            for (int t = 0; t < 4; t++)                                            \
                mma16816(acc[bm][t], al[bm], BFR[t].x, BFR[t].y);                  \
    } while (0)

    F_LDGA(0);
    F_LDGB(bE, 0);
    F_STSA(0u);
    __syncthreads();

    const uint32_t l4 = (uint32_t)(lid * 4);

#pragma unroll 1
    for (int c = 0; c < NCHUNK; c += 2) {
        if (c + 1 < NCHUNK) { F_LDGA((c + 1) * KCHUNK); F_LDGB(bO, c + 1); }
        F_CONSUME(0u, bE);
        if (c + 1 < NCHUNK) F_STSA(STAGE_BF);
        __syncthreads();

        if (c + 2 < NCHUNK) { F_LDGA((c + 2) * KCHUNK); F_LDGB(bE, c + 2); }
        F_CONSUME((uint32_t)STAGE_BF, bO);
        if (c + 2 < NCHUNK) F_STSA(0u);
        __syncthreads();
    }

    // ---- epilogue ----
    const float invL = (EPI != 0) ? g_scal[0] : 0.0f;
    const float th   = (EPI != 0) ? g_scal[1] : 0.0f;
    const int gid = lid >> 2, tig = lid & 3;
#pragma unroll
    for (int bm = 0; bm < 2; bm++) {
#pragma unroll
        for (int bn = 0; bn < 4; bn++) {
            const int n = col0 + wn * 32 + bn * 8 + tig * 2;
#pragma unroll
            for (int hr = 0; hr < 2; hr++) {
                const int m = row0 + wm * 32 + bm * 16 + gid + hr * 8;
                float ax = acc[bm][bn][hr * 2 + 0];
                float ay = acc[bm][bn][hr * 2 + 1];
                const size_t idx = (size_t)m * SDIM + n;
                if (EPI == 0) {
                    ax *= scale; ay *= scale;
                    float2 o; o.x = ax; o.y = ay;
                    *reinterpret_cast<float2*>(C + idx) = o;
                    if (SYM && mirror) {
                        C[(size_t)n * SDIM + m]       = ax;
                        C[(size_t)(n + 1) * SDIM + m] = ay;
                    }
                } else if (EPI == 1) {
                    // res in regs -> u store + delta FISTA update
                    float2 s  = *reinterpret_cast<const float2*>(src + idx);
                    float2 yv = *reinterpret_cast<const float2*>(Yg + idx);
                    float2 yd = *reinterpret_cast<const float2*>(ydl + idx);
                    float2 xd = *reinterpret_cast<const float2*>(xdl + idx);
                    float rx = yv.x - s.x * ax - yd.x;
                    float ry = yv.y - s.y * ay - yd.y;
                    float2 uu; uu.x = s.x * rx; uu.y = s.y * ry;
                    *reinterpret_cast<float2*>(C + idx) = uu;   // C = u buffer
                    float2 xnd, ynd;
                    xnd.x = softthr(yd.x + rx * invL, th);  ynd.x = xnd.x + mom * (xnd.x - xd.x);
                    xnd.y = softthr(yd.y + ry * invL, th);  ynd.y = xnd.y + mom * (xnd.y - xd.y);
                    *reinterpret_cast<float2*>(xdl + idx) = xnd;
                    *reinterpret_cast<float2*>(ydl + idx) = ynd;
                    if (outp) {
                        const size_t ob = (size_t)m * (2 * SDIM) + SDIM + n;
                        *reinterpret_cast<float2*>(outp + ob) = xnd;
                    }
                } else {
                    // theta FISTA update
                    float2 yt = *reinterpret_cast<const float2*>(yth + idx);
                    float2 xt = *reinterpret_cast<const float2*>(xth + idx);
                    float2 xn, yn;
                    xn.x = softthr(yt.x + ax * invL, th);  yn.x = xn.x + mom * (xn.x - xt.x);
                    xn.y = softthr(yt.y + ay * invL, th);  yn.y = xn.y + mom * (xn.y - xt.y);
                    *reinterpret_cast<float2*>(xth + idx) = xn;
                    *reinterpret_cast<float2*>(yth + idx) = yn;
                    if (outp) {
                        const size_t ob = (size_t)m * (2 * SDIM) + n;
                        *reinterpret_cast<float2*>(outp + ob) = xn;
                    }
                }
            }
        }
    }
}

// ---------------------------------------------------------------------------
// B-frag builder: F[(nt*NCHUNK + c)*32 + lane] = {hi_k0, hi_k8, lo_k0, lo_k8}
// ---------------------------------------------------------------------------
__global__ void build_bfrag(const float* __restrict__ B, uint4* __restrict__ F) {
    int l  = threadIdx.x & 31;
    int nt = blockIdx.x * 8 + (threadIdx.x >> 5);
    int c  = blockIdx.y;
    int n  = nt * 8 + (l >> 2);
    int k0 = c * KCHUNK + (l & 3) * 2;
    const float* row = B + (size_t)n * SDIM;
    uint4 w;
    uint32_t lz, lw;
    pack2(row[k0],     row[k0 + 1], w.x, lz);
    pack2(row[k0 + 8], row[k0 + 9], w.y, lw);
    w.z = lz; w.w = lw;
    F[((size_t)nt * NCHUNK + c) * 32 + l] = w;
}

// ---------------- helper kernels ----------------
__global__ void transpose_kernel(const float* __restrict__ in, float* __restrict__ out) {
    __shared__ float t[32][33];
    int bx = blockIdx.x * 32, by = blockIdx.y * 32;
    int x = bx + threadIdx.x;
#pragma unroll
    for (int i = threadIdx.y; i < 32; i += 8)
        t[i][threadIdx.x] = in[(size_t)(by + i) * SDIM + x];
    __syncthreads();
    int x2 = by + threadIdx.x;
#pragma unroll
    for (int i = threadIdx.y; i < 32; i += 8)
        out[(size_t)(bx + i) * SDIM + x2] = t[threadIdx.x][i];
}

// iter0: y=0 -> r=Y ; u=src*Y ; delta step0 (mom=0): xdl=ydl=soft(Y*invL, th)
__global__ void init_iter0_kernel(const float* __restrict__ src, const float* __restrict__ Yg,
                                  float* __restrict__ uv,
                                  float* __restrict__ xdl, float* __restrict__ ydl) {
    int i = blockIdx.x * blockDim.x + threadIdx.x;
    const float invL = g_scal[0], th = g_scal[1];
    float4 y = reinterpret_cast<const float4*>(Yg)[i];
    float4 s = reinterpret_cast<const float4*>(src)[i];
    float4 u; u.x = s.x * y.x; u.y = s.y * y.y; u.z = s.z * y.z; u.w = s.w * y.w;
    reinterpret_cast<float4*>(uv)[i] = u;
    float4 x;
    x.x = softthr(y.x * invL, th);
    x.y = softthr(y.y * invL, th);
    x.z = softthr(y.z * invL, th);
    x.w = softthr(y.w * invL, th);
    reinterpret_cast<float4*>(xdl)[i] = x;
    reinterpret_cast<float4*>(ydl)[i] = x;
}

__global__ void fill_kernel() {
    int i = blockIdx.x * blockDim.x + threadIdx.x;
    if (i < SDIM) {
        unsigned h = (unsigned)i * 2654435761u;
        h ^= h >> 13; h *= 2246822519u; h ^= h >> 16;
        g_vec[i] = (float)(h & 0xFFFF) / 65536.0f - 0.5f;
    }
}

__global__ void matvec_kernel(const float* __restrict__ H,
                              const float* __restrict__ x,
                              float* __restrict__ y) {
    int row = blockIdx.x;
    const float* hr = H + (size_t)row * SDIM;
    float s = 0.0f;
    for (int j = threadIdx.x; j < SDIM; j += 256) s += hr[j] * x[j];
#pragma unroll
    for (int o = 16; o > 0; o >>= 1) s += __shfl_xor_sync(0xffffffffu, s, o);
    __shared__ float part[8];
    int w = threadIdx.x >> 5;
    if ((threadIdx.x & 31) == 0) part[w] = s;
    __syncthreads();
    if (threadIdx.x == 0) {
        float t = 0.0f;
#pragma unroll
        for (int k = 0; k < 8; k++) t += part[k];
        y[row] = t;
    }
}

__global__ void normalize_kernel(const float* __restrict__ w, float* __restrict__ v) {
    float ss = 0.0f;
    for (int i = threadIdx.x; i < SDIM; i += 256) { float t = w[i]; ss += t * t; }
#pragma unroll
    for (int o = 16; o > 0; o >>= 1) ss += __shfl_xor_sync(0xffffffffu, ss, o);
    __shared__ float part[8];
    __shared__ float s_inv;
    int wd = threadIdx.x >> 5;
    if ((threadIdx.x & 31) == 0) part[wd] = ss;
    __syncthreads();
    if (threadIdx.x == 0) {
        float t = 0.0f;
        for (int i = 0; i < 8; i++) t += part[i];
        s_inv = rsqrtf(t);
    }
    __syncthreads();
    float inv = s_inv;
    for (int i = threadIdx.x; i < SDIM; i += 256) v[i] = w[i] * inv;
}

// Rayleigh on G'^64 (G' = G/4): L = 4 * lam^(1/64); writes 1/L and thresh.
__global__ void finalize_kernel(const float* __restrict__ v,
                                const float* __restrict__ w,
                                const float* __restrict__ alpha) {
    float num = 0.0f, den = 0.0f;
    for (int i = threadIdx.x; i < SDIM; i += 256) { num += v[i] * w[i]; den += v[i] * v[i]; }
#pragma unroll
    for (int o = 16; o > 0; o >>= 1) {
        num += __shfl_xor_sync(0xffffffffu, num, o);
        den += __shfl_xor_sync(0xffffffffu, den, o);
    }
    __shared__ float pn[8], pd[8];
    int wd = threadIdx.x >> 5;
    if ((threadIdx.x & 31) == 0) { pn[wd] = num; pd[wd] = den; }
    __syncthreads();
    if (threadIdx.x == 0) {
        double n = 0.0, d = 0.0;
        for (int i = 0; i < 8; i++) { n += pn[i]; d += pd[i]; }
        double lam = n / d;
        double L = 4.0 * pow(lam, 1.0 / 64.0);
        g_scal[0] = (float)(1.0 / L);
        g_scal[1] = (float)((double)alpha[0] * 0.5 / L);
    }
}

#define NSYMT (136 * 2)
#define FNULL nullptr, nullptr, nullptr, nullptr, nullptr, nullptr, nullptr, 0.0f

extern "C" void kernel_launch(void* const* d_in, const int* in_sizes, int n_in,
                              void* d_out, int out_size) {
    (void)in_sizes; (void)n_in; (void)out_size;
    const float* src   = (const float*)d_in[0];
    const float* Y     = (const float*)d_in[1];
    const float* W     = (const float*)d_in[2];
    const float* alpha = (const float*)d_in[3];
    float* out = (float*)d_out;

    float *yth, *ydl, *xth, *xdl, *u, *WT, *MA, *MB, *vec, *wvec;
    uint4 *FW, *FWT, *FMA, *FMB;
    cudaGetSymbolAddress((void**)&yth,  g_yth);
    cudaGetSymbolAddress((void**)&ydl,  g_ydl);
    cudaGetSymbolAddress((void**)&xth,  g_xth);
    cudaGetSymbolAddress((void**)&xdl,  g_xdl);
    cudaGetSymbolAddress((void**)&u,    g_u);
    cudaGetSymbolAddress((void**)&WT,   g_WT);
    cudaGetSymbolAddress((void**)&MA,   g_MA);
    cudaGetSymbolAddress((void**)&MB,   g_MB);
    cudaGetSymbolAddress((void**)&FW,   g_FW);
    cudaGetSymbolAddress((void**)&FWT,  g_FWT);
    cudaGetSymbolAddress((void**)&FMA,  g_FMA);
    cudaGetSymbolAddress((void**)&FMB,  g_FMB);
    cudaGetSymbolAddress((void**)&vec,  g_vec);
    cudaGetSymbolAddress((void**)&wvec, g_wvec);

    // WT = W^T, then B-frag splits of W and WT
    transpose_kernel<<<dim3(64, 64), dim3(32, 8)>>>(W, WT);
    build_bfrag<<<dim3(NTTILES / 8, NCHUNK), 256>>>(W, FW);
    build_bfrag<<<dim3(NTTILES / 8, NCHUNK), 256>>>(WT, FWT);

    // eigen chain: G' = (W^T W)/4, then 6 squarings -> G'^64 in MA.
    gemm_bf<0, 1><<<NSYMT, NTHREADS, SMEM_BF>>>(WT, FWT, MA, 0.25f, FNULL);
    build_bfrag<<<dim3(NTTILES / 8, NCHUNK), 256>>>(MA, FMA);
    gemm_bf<0, 1><<<NSYMT, NTHREADS, SMEM_BF>>>(MA, FMA, MB, 1.0f, FNULL);
    build_bfrag<<<dim3(NTTILES / 8, NCHUNK), 256>>>(MB, FMB);
    gemm_bf<0, 1><<<NSYMT, NTHREADS, SMEM_BF>>>(MB, FMB, MA, 1.0f, FNULL);
    build_bfrag<<<dim3(NTTILES / 8, NCHUNK), 256>>>(MA, FMA);
    gemm_bf<0, 1><<<NSYMT, NTHREADS, SMEM_BF>>>(MA, FMA, MB, 1.0f, FNULL);
    build_bfrag<<<dim3(NTTILES / 8, NCHUNK), 256>>>(MB, FMB);
    gemm_bf<0, 1><<<NSYMT, NTHREADS, SMEM_BF>>>(MB, FMB, MA, 1.0f, FNULL);
    build_bfrag<<<dim3(NTTILES / 8, NCHUNK), 256>>>(MA, FMA);
    gemm_bf<0, 1><<<NSYMT, NTHREADS, SMEM_BF>>>(MA, FMA, MB, 1.0f, FNULL);
    build_bfrag<<<dim3(NTTILES / 8, NCHUNK), 256>>>(MB, FMB);
    gemm_bf<0, 1><<<NSYMT, NTHREADS, SMEM_BF>>>(MB, FMB, MA, 1.0f, FNULL);

    // power iteration + Rayleigh on G'^64
    fill_kernel<<<(SDIM + 255) / 256, 256>>>();
    for (int i = 0; i < 2; i++) {
        for (int jj = 0; jj < 7; jj++) {
            matvec_kernel<<<SDIM, 256>>>(MA, vec, wvec);
            float* tmp = vec; vec = wvec; wvec = tmp;
        }
        matvec_kernel<<<SDIM, 256>>>(MA, vec, wvec);
        normalize_kernel<<<1, 256>>>(wvec, vec);
    }
    matvec_kernel<<<SDIM, 256>>>(MA, vec, wvec);
    finalize_kernel<<<1, 256>>>(vec, wvec, alpha);

    // FISTA state init: theta halves zero; iter0 shortcut for u + delta step
    size_t bytes = (size_t)BATCH * SDIM * sizeof(float);
    cudaMemsetAsync(yth, 0, bytes);
    cudaMemsetAsync(xth, 0, bytes);
    init_iter0_kernel<<<(BATCH * SDIM / 4 + 255) / 256, 256>>>(src, Y, u, xdl, ydl);

    dim3 ga(SDIM / 128, BATCH / 64);   // 16 x 16 = 256 CTAs

    float t = 1.0f;
    for (int it = 0; it < N_ITER; it++) {
        float tn  = (1.0f + sqrtf(1.0f + 4.0f * t * t)) * 0.5f;
        float mom = (t - 1.0f) / tn;
        t = tn;
        float* op = (it == N_ITER - 1) ? out : nullptr;

        if (it > 0) {
            // GEMM1: Z = yth*W^T ; r = Y - src*Z - ydl (regs) ; u = src*r ;
            //        delta soft-threshold + momentum (+out delta half)
            gemm_bf<1, 0><<<ga, NTHREADS, SMEM_BF>>>(yth, FW, u, 0.0f,
                src, Y, nullptr, nullptr, xdl, ydl, op, mom);
        }
        // GEMM2: g = W^T u ; theta soft-threshold + momentum (+out theta half)
        gemm_bf<2, 0><<<ga, NTHREADS, SMEM_BF>>>(u, FWT, nullptr, 0.0f,
            nullptr, nullptr, xth, yth, nullptr, nullptr, op, mom);
    }
}

// round 14
// speedup vs baseline: 1.2150x; 1.1598x over previous
#include <cuda_runtime.h>
#include <math.h>
#include <stdint.h>

#define BATCH   1024
#define SDIM    2048
#define N_ITER  16
#define KCHUNK  16
#define NCHUNK  (SDIM / KCHUNK)    // 128
#define NTTILES (SDIM / 8)         // 256

// ---------------- static device scratch ----------------
__device__ __align__(256) float g_yth[BATCH * SDIM];
__device__ __align__(256) float g_ydl[BATCH * SDIM];
__device__ __align__(256) float g_xth[BATCH * SDIM];
__device__ __align__(256) float g_xdl[BATCH * SDIM];
__device__ __align__(256) float g_u  [BATCH * SDIM];
__device__ __align__(256) float g_WT [SDIM * SDIM];
__device__ __align__(256) float g_MA [SDIM * SDIM];
__device__ __align__(256) float g_MB [SDIM * SDIM];
__device__ __align__(256) uint4 g_FW [NTTILES * NCHUNK * 32];   // W  B-frags
__device__ __align__(256) uint4 g_FWT[NTTILES * NCHUNK * 32];   // WT B-frags
__device__ __align__(256) uint4 g_FMA[NTTILES * NCHUNK * 32];   // eigen intermediate frags
__device__ __align__(256) uint4 g_FMB[NTTILES * NCHUNK * 32];
__device__ __align__(256) float g_vec [SDIM];
__device__ __align__(256) float g_wvec[SDIM];
__device__ float g_scal[4];   // [0] = 1/L, [1] = thresh

// A-side smem: Ahi[0,2K) Alo[2K,4K), two stages
#define STAGE_BF   4096
#define SMEM_BF    (2 * STAGE_BF)  // 8 KB

static __device__ __forceinline__ uint32_t smem_u32(const void* p) {
    uint32_t a;
    asm("{ .reg .u64 t; cvta.to.shared.u64 t, %1; cvt.u32.u64 %0, t; }" : "=r"(a) : "l"(p));
    return a;
}
static __device__ __forceinline__ uint32_t lds32(uint32_t a) {
    uint32_t v; asm volatile("ld.shared.b32 %0, [%1];" : "=r"(v) : "r"(a)); return v;
}
static __device__ __forceinline__ void sts64(uint32_t a, uint32_t v0, uint32_t v1) {
    asm volatile("st.shared.v2.b32 [%0], {%1,%2};" :: "r"(a), "r"(v0), "r"(v1));
}
static __device__ __forceinline__ void mma16816(float* d, const uint32_t* a,
                                                uint32_t b0, uint32_t b1) {
    asm volatile(
        "mma.sync.aligned.m16n8k16.row.col.f32.bf16.bf16.f32 "
        "{%0,%1,%2,%3}, {%4,%5,%6,%7}, {%8,%9}, {%0,%1,%2,%3};"
        : "+f"(d[0]), "+f"(d[1]), "+f"(d[2]), "+f"(d[3])
        : "r"(a[0]), "r"(a[1]), "r"(a[2]), "r"(a[3]), "r"(b0), "r"(b1));
}

// split float4 -> 2 packed bf16x2 hi (truncated) + 2 lo (rounded residual)
static __device__ __forceinline__ void split4(float4 v, uint32_t& h0, uint32_t& h1,
                                              uint32_t& l0, uint32_t& l1) {
    uint32_t u0 = __float_as_uint(v.x), u1 = __float_as_uint(v.y);
    uint32_t u2 = __float_as_uint(v.z), u3 = __float_as_uint(v.w);
    h0 = __byte_perm(u0, u1, 0x7632);
    h1 = __byte_perm(u2, u3, 0x7632);
    float a0 = v.x - __uint_as_float(u0 & 0xFFFF0000u);
    float a1 = v.y - __uint_as_float(u1 & 0xFFFF0000u);
    float a2 = v.z - __uint_as_float(u2 & 0xFFFF0000u);
    float a3 = v.w - __uint_as_float(u3 & 0xFFFF0000u);
    asm("cvt.rn.bf16x2.f32 %0, %1, %2;" : "=r"(l0) : "f"(a1), "f"(a0));
    asm("cvt.rn.bf16x2.f32 %0, %1, %2;" : "=r"(l1) : "f"(a3), "f"(a2));
}

// pack pair (x -> low half, y -> high half)
static __device__ __forceinline__ void pack2(float x, float y, uint32_t& h, uint32_t& l) {
    uint32_t ux = __float_as_uint(x), uy = __float_as_uint(y);
    h = __byte_perm(ux, uy, 0x7632);
    float r0 = x - __uint_as_float(ux & 0xFFFF0000u);
    float r1 = y - __uint_as_float(uy & 0xFFFF0000u);
    asm("cvt.rn.bf16x2.f32 %0, %1, %2;" : "=r"(l) : "f"(r1), "f"(r0));
}

static __device__ __forceinline__ float softthr(float v, float th) {
    float a = fabsf(v) - th;
    return a > 0.0f ? copysignf(a, v) : 0.0f;
}

// ---------------------------------------------------------------------------
// Unified GEMM (R11): C[m,n] = sum_k A[m,k]*B[n,k], K=2048. CTA 64(M)x128(N),
// 4 warps (2x2), warp tile 32x64. A: fp32 via smem (split in-kernel);
// B: pre-split frag array via LDG, register double-buffered.
// SYM=1 (EPI 0): triangular macro grid + mirror; C = acc*scale.
// EPI 1: GEMM1 epilogue: res in regs -> u, delta soft-threshold update (+out)
// EPI 2: GEMM2 epilogue: theta soft-threshold update (+out)
// ---------------------------------------------------------------------------
template<int EPI, int SYM>
__global__ void __launch_bounds__(128, 2)
gemm_bf(const float* __restrict__ A, const uint4* __restrict__ FB,
        float* __restrict__ C, float scale,
        const float* __restrict__ src, const float* __restrict__ Yg,
        float* __restrict__ xth, float* __restrict__ yth,
        float* __restrict__ xdl, float* __restrict__ ydl,
        float* __restrict__ outp, float mom)
{
    extern __shared__ char smem[];
    const uint32_t sb = smem_u32(smem);
    const int tid = threadIdx.x;
    const int wid = tid >> 5, lid = tid & 31;
    const int wm = wid & 1, wn = wid >> 1;

    int row0, col0;
    bool mirror = false;
    if (SYM) {
        int bid = blockIdx.x;
        int mac = bid >> 1, half0 = bid & 1;
        int by = (int)((sqrtf(8.0f * mac + 1.0f) - 1.0f) * 0.5f);
        while ((by + 1) * (by + 2) / 2 <= mac) by++;
        while (by * (by + 1) / 2 > mac) by--;
        int bx = mac - by * (by + 1) / 2;
        row0 = by * 128 + half0 * 64;
        col0 = bx * 128;
        mirror = (bx != by);
    } else {
        row0 = blockIdx.y * 64;
        col0 = blockIdx.x * 128;
    }

    // A producer mapping (coalesced LDG, conflict-free STS.64)
    const int qa = tid & 3;
    const int rbase = tid >> 2;
    const int hp = qa >> 1, q1 = qa & 1;
    uint32_t aOff[2];
#pragma unroll
    for (int p = 0; p < 2; p++) {
        int r = rbase + 32 * p;
        int mt = r >> 4, rr = r & 15, rrq = rr & 7, r8 = rr >> 3;
        aOff[p] = (uint32_t)(((mt * 4 + hp * 2 + r8) * 32 + rrq * 4 + 2 * q1) * 4);
    }
    const float* Abase = A + (size_t)(row0 + rbase) * SDIM + qa * 4;

    // B fragment base for this warp: n-tiles (col0>>3)+wn*8 ..+7
    const uint4* Fbase = FB + ((size_t)((col0 >> 3) + wn * 8) * NCHUNK) * 32 + lid;

    float acc[2][8][4];
#pragma unroll
    for (int i = 0; i < 2; i++)
#pragma unroll
        for (int j = 0; j < 8; j++)
#pragma unroll
            for (int q = 0; q < 4; q++) acc[i][j][q] = 0.0f;

    float4 pA[2];
    uint4 bE[8], bO[8];

#define F_LDGA(kt)                                                                 \
    do {                                                                           \
        _Pragma("unroll")                                                          \
        for (int p = 0; p < 2; p++)                                                \
            pA[p] = *reinterpret_cast<const float4*>(Abase + (size_t)(32 * p) * SDIM + (kt)); \
    } while (0)

#define F_STSA(stoff)                                                              \
    do {                                                                           \
        _Pragma("unroll")                                                          \
        for (int p = 0; p < 2; p++) {                                              \
            uint32_t h0, h1, l0, l1;                                               \
            split4(pA[p], h0, h1, l0, l1);                                         \
            sts64(sb + (stoff) + aOff[p], h0, h1);                                 \
            sts64(sb + (stoff) + 2048u + aOff[p], l0, l1);                         \
        }                                                                          \
    } while (0)

#define F_LDGB(dst, cc)                                                            \
    do {                                                                           \
        _Pragma("unroll")                                                          \
        for (int t = 0; t < 8; t++)                                                \
            dst[t] = Fbase[((size_t)t * NCHUNK + (cc)) * 32];                      \
    } while (0)

#define F_CONSUME(stoff, BFR)                                                      \
    do {                                                                           \
        uint32_t ah[2][4], al[2][4];                                               \
        _Pragma("unroll")                                                          \
        for (int bm = 0; bm < 2; bm++) {                                           \
            int mt = wm * 2 + bm;                                                  \
            uint32_t ab = sb + (stoff) + (uint32_t)((mt * 4) * 128) + l4;          \
            _Pragma("unroll")                                                      \
            for (int wi = 0; wi < 4; wi++) {                                       \
                ah[bm][wi] = lds32(ab + wi * 128);                                 \
                al[bm][wi] = lds32(ab + 2048u + wi * 128);                         \
            }                                                                      \
        }                                                                          \
        _Pragma("unroll")                                                          \
        for (int bm = 0; bm < 2; bm++)                                             \
            _Pragma("unroll")                                                      \
            for (int t = 0; t < 8; t++)                                            \
                mma16816(acc[bm][t], ah[bm], BFR[t].x, BFR[t].y);                  \
        _Pragma("unroll")                                                          \
        for (int bm = 0; bm < 2; bm++)                                             \
            _Pragma("unroll")                                                      \
            for (int t = 0; t < 8; t++)                                            \
                mma16816(acc[bm][t], ah[bm], BFR[t].z, BFR[t].w);                  \
        _Pragma("unroll")                                                          \
        for (int bm = 0; bm < 2; bm++)                                             \
            _Pragma("unroll")                                                      \
            for (int t = 0; t < 8; t++)                                            \
                mma16816(acc[bm][t], al[bm], BFR[t].x, BFR[t].y);                  \
    } while (0)

    F_LDGA(0);
    F_LDGB(bE, 0);
    F_STSA(0u);
    __syncthreads();

    const uint32_t l4 = (uint32_t)(lid * 4);

#pragma unroll 1
    for (int c = 0; c < NCHUNK; c += 2) {
        if (c + 1 < NCHUNK) { F_LDGA((c + 1) * KCHUNK); F_LDGB(bO, c + 1); }
        F_CONSUME(0u, bE);
        if (c + 1 < NCHUNK) F_STSA(STAGE_BF);
        __syncthreads();

        if (c + 2 < NCHUNK) { F_LDGA((c + 2) * KCHUNK); F_LDGB(bE, c + 2); }
        F_CONSUME((uint32_t)STAGE_BF, bO);
        if (c + 2 < NCHUNK) F_STSA(0u);
        __syncthreads();
    }

    // ---- epilogue ----
    const float invL = (EPI != 0) ? g_scal[0] : 0.0f;
    const float th   = (EPI != 0) ? g_scal[1] : 0.0f;
    const int gid = lid >> 2, tig = lid & 3;
#pragma unroll
    for (int bm = 0; bm < 2; bm++) {
#pragma unroll
        for (int bn = 0; bn < 8; bn++) {
            const int n = col0 + wn * 64 + bn * 8 + tig * 2;
#pragma unroll
            for (int hr = 0; hr < 2; hr++) {
                const int m = row0 + wm * 32 + bm * 16 + gid + hr * 8;
                float ax = acc[bm][bn][hr * 2 + 0];
                float ay = acc[bm][bn][hr * 2 + 1];
                const size_t idx = (size_t)m * SDIM + n;
                if (EPI == 0) {
                    ax *= scale; ay *= scale;
                    float2 o; o.x = ax; o.y = ay;
                    *reinterpret_cast<float2*>(C + idx) = o;
                    if (SYM && mirror) {
                        C[(size_t)n * SDIM + m]       = ax;
                        C[(size_t)(n + 1) * SDIM + m] = ay;
                    }
                } else if (EPI == 1) {
                    // res in regs -> u store + delta FISTA update
                    float2 s  = *reinterpret_cast<const float2*>(src + idx);
                    float2 yv = *reinterpret_cast<const float2*>(Yg + idx);
                    float2 yd = *reinterpret_cast<const float2*>(ydl + idx);
                    float2 xd = *reinterpret_cast<const float2*>(xdl + idx);
                    float rx = yv.x - s.x * ax - yd.x;
                    float ry = yv.y - s.y * ay - yd.y;
                    float2 uu; uu.x = s.x * rx; uu.y = s.y * ry;
                    *reinterpret_cast<float2*>(C + idx) = uu;   // C = u buffer
                    float2 xnd, ynd;
                    xnd.x = softthr(yd.x + rx * invL, th);  ynd.x = xnd.x + mom * (xnd.x - xd.x);
                    xnd.y = softthr(yd.y + ry * invL, th);  ynd.y = xnd.y + mom * (xnd.y - xd.y);
                    *reinterpret_cast<float2*>(xdl + idx) = xnd;
                    *reinterpret_cast<float2*>(ydl + idx) = ynd;
                    if (outp) {
                        const size_t ob = (size_t)m * (2 * SDIM) + SDIM + n;
                        *reinterpret_cast<float2*>(outp + ob) = xnd;
                    }
                } else {
                    // theta FISTA update
                    float2 yt = *reinterpret_cast<const float2*>(yth + idx);
                    float2 xt = *reinterpret_cast<const float2*>(xth + idx);
                    float2 xn, yn;
                    xn.x = softthr(yt.x + ax * invL, th);  yn.x = xn.x + mom * (xn.x - xt.x);
                    xn.y = softthr(yt.y + ay * invL, th);  yn.y = xn.y + mom * (xn.y - xt.y);
                    *reinterpret_cast<float2*>(xth + idx) = xn;
                    *reinterpret_cast<float2*>(yth + idx) = yn;
                    if (outp) {
                        const size_t ob = (size_t)m * (2 * SDIM) + n;
                        *reinterpret_cast<float2*>(outp + ob) = xn;
                    }
                }
            }
        }
    }
}

// ---------------------------------------------------------------------------
// B-frag builder: F[(nt*NCHUNK + c)*32 + lane] = {hi_k0, hi_k8, lo_k0, lo_k8}
// ---------------------------------------------------------------------------
__global__ void build_bfrag(const float* __restrict__ B, uint4* __restrict__ F) {
    int l  = threadIdx.x & 31;
    int nt = blockIdx.x * 8 + (threadIdx.x >> 5);
    int c  = blockIdx.y;
    int n  = nt * 8 + (l >> 2);
    int k0 = c * KCHUNK + (l & 3) * 2;
    const float* row = B + (size_t)n * SDIM;
    uint4 w;
    uint32_t lz, lw;
    pack2(row[k0],     row[k0 + 1], w.x, lz);
    pack2(row[k0 + 8], row[k0 + 9], w.y, lw);
    w.z = lz; w.w = lw;
    F[((size_t)nt * NCHUNK + c) * 32 + l] = w;
}

// ---------------- helper kernels ----------------
__global__ void transpose_kernel(const float* __restrict__ in, float* __restrict__ out) {
    __shared__ float t[32][33];
    int bx = blockIdx.x * 32, by = blockIdx.y * 32;
    int x = bx + threadIdx.x;
#pragma unroll
    for (int i = threadIdx.y; i < 32; i += 8)
        t[i][threadIdx.x] = in[(size_t)(by + i) * SDIM + x];
    __syncthreads();
    int x2 = by + threadIdx.x;
#pragma unroll
    for (int i = threadIdx.y; i < 32; i += 8)
        out[(size_t)(bx + i) * SDIM + x2] = t[threadIdx.x][i];
}

// iter0: y=0 -> r=Y ; u=src*Y ; delta step0 (mom=0): xdl=ydl=soft(Y*invL, th)
__global__ void init_iter0_kernel(const float* __restrict__ src, const float* __restrict__ Yg,
                                  float* __restrict__ uv,
                                  float* __restrict__ xdl, float* __restrict__ ydl) {
    int i = blockIdx.x * blockDim.x + threadIdx.x;
    const float invL = g_scal[0], th = g_scal[1];
    float4 y = reinterpret_cast<const float4*>(Yg)[i];
    float4 s = reinterpret_cast<const float4*>(src)[i];
    float4 u; u.x = s.x * y.x; u.y = s.y * y.y; u.z = s.z * y.z; u.w = s.w * y.w;
    reinterpret_cast<float4*>(uv)[i] = u;
    float4 x;
    x.x = softthr(y.x * invL, th);
    x.y = softthr(y.y * invL, th);
    x.z = softthr(y.z * invL, th);
    x.w = softthr(y.w * invL, th);
    reinterpret_cast<float4*>(xdl)[i] = x;
    reinterpret_cast<float4*>(ydl)[i] = x;
}

__global__ void fill_kernel() {
    int i = blockIdx.x * blockDim.x + threadIdx.x;
    if (i < SDIM) {
        unsigned h = (unsigned)i * 2654435761u;
        h ^= h >> 13; h *= 2246822519u; h ^= h >> 16;
        g_vec[i] = (float)(h & 0xFFFF) / 65536.0f - 0.5f;
    }
}

__global__ void matvec_kernel(const float* __restrict__ H,
                              const float* __restrict__ x,
                              float* __restrict__ y) {
    int row = blockIdx.x;
    const float* hr = H + (size_t)row * SDIM;
    float s = 0.0f;
    for (int j = threadIdx.x; j < SDIM; j += 256) s += hr[j] * x[j];
#pragma unroll
    for (int o = 16; o > 0; o >>= 1) s += __shfl_xor_sync(0xffffffffu, s, o);
    __shared__ float part[8];
    int w = threadIdx.x >> 5;
    if ((threadIdx.x & 31) == 0) part[w] = s;
    __syncthreads();
    if (threadIdx.x == 0) {
        float t = 0.0f;
#pragma unroll
        for (int k = 0; k < 8; k++) t += part[k];
        y[row] = t;
    }
}

__global__ void normalize_kernel(const float* __restrict__ w, float* __restrict__ v) {
    float ss = 0.0f;
    for (int i = threadIdx.x; i < SDIM; i += 256) { float t = w[i]; ss += t * t; }
#pragma unroll
    for (int o = 16; o > 0; o >>= 1) ss += __shfl_xor_sync(0xffffffffu, ss, o);
    __shared__ float part[8];
    __shared__ float s_inv;
    int wd = threadIdx.x >> 5;
    if ((threadIdx.x & 31) == 0) part[wd] = ss;
    __syncthreads();
    if (threadIdx.x == 0) {
        float t = 0.0f;
        for (int i = 0; i < 8; i++) t += part[i];
        s_inv = rsqrtf(t);
    }
    __syncthreads();
    float inv = s_inv;
    for (int i = threadIdx.x; i < SDIM; i += 256) v[i] = w[i] * inv;
}

// Rayleigh on G'^64 (G' = G/4): L = 4 * lam^(1/64); writes 1/L and thresh.
__global__ void finalize_kernel(const float* __restrict__ v,
                                const float* __restrict__ w,
                                const float* __restrict__ alpha) {
    float num = 0.0f, den = 0.0f;
    for (int i = threadIdx.x; i < SDIM; i += 256) { num += v[i] * w[i]; den += v[i] * v[i]; }
#pragma unroll
    for (int o = 16; o > 0; o >>= 1) {
        num += __shfl_xor_sync(0xffffffffu, num, o);
        den += __shfl_xor_sync(0xffffffffu, den, o);
    }
    __shared__ float pn[8], pd[8];
    int wd = threadIdx.x >> 5;
    if ((threadIdx.x & 31) == 0) { pn[wd] = num; pd[wd] = den; }
    __syncthreads();
    if (threadIdx.x == 0) {
        double n = 0.0, d = 0.0;
        for (int i = 0; i < 8; i++) { n += pn[i]; d += pd[i]; }
        double lam = n / d;
        double L = 4.0 * pow(lam, 1.0 / 64.0);
        g_scal[0] = (float)(1.0 / L);
        g_scal[1] = (float)((double)alpha[0] * 0.5 / L);
    }
}

#define NSYMT (136 * 2)
#define FNULL nullptr, nullptr, nullptr, nullptr, nullptr, nullptr, nullptr, 0.0f

extern "C" void kernel_launch(void* const* d_in, const int* in_sizes, int n_in,
                              void* d_out, int out_size) {
    (void)in_sizes; (void)n_in; (void)out_size;
    const float* src   = (const float*)d_in[0];
    const float* Y     = (const float*)d_in[1];
    const float* W     = (const float*)d_in[2];
    const float* alpha = (const float*)d_in[3];
    float* out = (float*)d_out;

    float *yth, *ydl, *xth, *xdl, *u, *WT, *MA, *MB, *vec, *wvec;
    uint4 *FW, *FWT, *FMA, *FMB;
    cudaGetSymbolAddress((void**)&yth,  g_yth);
    cudaGetSymbolAddress((void**)&ydl,  g_ydl);
    cudaGetSymbolAddress((void**)&xth,  g_xth);
    cudaGetSymbolAddress((void**)&xdl,  g_xdl);
    cudaGetSymbolAddress((void**)&u,    g_u);
    cudaGetSymbolAddress((void**)&WT,   g_WT);
    cudaGetSymbolAddress((void**)&MA,   g_MA);
    cudaGetSymbolAddress((void**)&MB,   g_MB);
    cudaGetSymbolAddress((void**)&FW,   g_FW);
    cudaGetSymbolAddress((void**)&FWT,  g_FWT);
    cudaGetSymbolAddress((void**)&FMA,  g_FMA);
    cudaGetSymbolAddress((void**)&FMB,  g_FMB);
    cudaGetSymbolAddress((void**)&vec,  g_vec);
    cudaGetSymbolAddress((void**)&wvec, g_wvec);

    // WT = W^T, then B-frag splits of W and WT
    transpose_kernel<<<dim3(64, 64), dim3(32, 8)>>>(W, WT);
    build_bfrag<<<dim3(NTTILES / 8, NCHUNK), 256>>>(W, FW);
    build_bfrag<<<dim3(NTTILES / 8, NCHUNK), 256>>>(WT, FWT);

    // eigen chain: G' = (W^T W)/4, then 6 squarings -> G'^64 in MA.
    gemm_bf<0, 1><<<NSYMT, 128, SMEM_BF>>>(WT, FWT, MA, 0.25f, FNULL);
    build_bfrag<<<dim3(NTTILES / 8, NCHUNK), 256>>>(MA, FMA);
    gemm_bf<0, 1><<<NSYMT, 128, SMEM_BF>>>(MA, FMA, MB, 1.0f, FNULL);
    build_bfrag<<<dim3(NTTILES / 8, NCHUNK), 256>>>(MB, FMB);
    gemm_bf<0, 1><<<NSYMT, 128, SMEM_BF>>>(MB, FMB, MA, 1.0f, FNULL);
    build_bfrag<<<dim3(NTTILES / 8, NCHUNK), 256>>>(MA, FMA);
    gemm_bf<0, 1><<<NSYMT, 128, SMEM_BF>>>(MA, FMA, MB, 1.0f, FNULL);
    build_bfrag<<<dim3(NTTILES / 8, NCHUNK), 256>>>(MB, FMB);
    gemm_bf<0, 1><<<NSYMT, 128, SMEM_BF>>>(MB, FMB, MA, 1.0f, FNULL);
    build_bfrag<<<dim3(NTTILES / 8, NCHUNK), 256>>>(MA, FMA);
    gemm_bf<0, 1><<<NSYMT, 128, SMEM_BF>>>(MA, FMA, MB, 1.0f, FNULL);
    build_bfrag<<<dim3(NTTILES / 8, NCHUNK), 256>>>(MB, FMB);
    gemm_bf<0, 1><<<NSYMT, 128, SMEM_BF>>>(MB, FMB, MA, 1.0f, FNULL);

    // power iteration + Rayleigh on G'^64: 10 matvecs, normalize mid-way
    fill_kernel<<<(SDIM + 255) / 256, 256>>>();
    for (int jj = 0; jj < 4; jj++) {
        matvec_kernel<<<SDIM, 256>>>(MA, vec, wvec);
        float* tmp = vec; vec = wvec; wvec = tmp;
    }
    matvec_kernel<<<SDIM, 256>>>(MA, vec, wvec);
    normalize_kernel<<<1, 256>>>(wvec, vec);
    for (int jj = 0; jj < 4; jj++) {
        matvec_kernel<<<SDIM, 256>>>(MA, vec, wvec);
        float* tmp = vec; vec = wvec; wvec = tmp;
    }
    matvec_kernel<<<SDIM, 256>>>(MA, vec, wvec);
    finalize_kernel<<<1, 256>>>(vec, wvec, alpha);

    // FISTA state init: theta halves zero; iter0 shortcut for u + delta step
    size_t bytes = (size_t)BATCH * SDIM * sizeof(float);
    cudaMemsetAsync(yth, 0, bytes);
    cudaMemsetAsync(xth, 0, bytes);
    init_iter0_kernel<<<(BATCH * SDIM / 4 + 255) / 256, 256>>>(src, Y, u, xdl, ydl);

    dim3 ga(SDIM / 128, BATCH / 64);   // 16 x 16 = 256 CTAs

    float t = 1.0f;
    for (int it = 0; it < N_ITER; it++) {
        float tn  = (1.0f + sqrtf(1.0f + 4.0f * t * t)) * 0.5f;
        float mom = (t - 1.0f) / tn;
        t = tn;
        float* op = (it == N_ITER - 1) ? out : nullptr;

        if (it > 0) {
            // GEMM1: Z = yth*W^T ; r = Y - src*Z - ydl (regs) ; u = src*r ;
            //        delta soft-threshold + momentum (+out delta half)
            gemm_bf<1, 0><<<ga, 128, SMEM_BF>>>(yth, FW, u, 0.0f,
                src, Y, nullptr, nullptr, xdl, ydl, op, mom);
        }
        // GEMM2: g = W^T u ; theta soft-threshold + momentum (+out theta half)
        gemm_bf<2, 0><<<ga, 128, SMEM_BF>>>(u, FWT, nullptr, 0.0f,
            nullptr, nullptr, xth, yth, nullptr, nullptr, op, mom);
    }
}